// round 9
// baseline (speedup 1.0000x reference)
#include <cuda_runtime.h>
#include <cstdint>

// ---------------- scratch (static device globals; no allocation) ----------------
__device__ __align__(16) float g_wav[64 * 196 * 768];   // channel-last [b][p][768]
__device__ __align__(16) float g_sp2[64 * 196 * 192];   // channel-last [b][p][192]
__device__ __align__(16) float g_wcomp[192 * 3 * 31 * 31];
__device__ __align__(16) float g_bias[192 * 4];

// extended-K bf16 operands (u32 = 2 bf16).
// gemm2: K=2883 pad 2944, K'=8832, KU2=4416 u32/row
// gemm3: K=8640 (tap-major reorder), K'=25920, KU3=12960 u32/row
// patches ext = [hi | hi | lo] ; weights ext = [hi | lo | hi]
__device__ __align__(16) unsigned g_A2e[192 * 4416];
__device__ __align__(16) unsigned g_A3e[768 * 12960];
__device__ __align__(16) unsigned g_B2e[12544u * 4416];
__device__ __align__(16) unsigned g_B3e[3200 * 12960];

// ---------------- helpers ----------------
__device__ __forceinline__ unsigned f2bf(float f) {
    unsigned u = __float_as_uint(f);
    return (u + 0x7fffu + ((u >> 16) & 1u)) >> 16;
}
__device__ __forceinline__ void split2(float v0, float v1, unsigned& hi, unsigned& lo) {
    unsigned h0 = f2bf(v0), h1 = f2bf(v1);
    float l0 = v0 - __uint_as_float(h0 << 16);
    float l1 = v1 - __uint_as_float(h1 << 16);
    hi = h0 | (h1 << 16);
    lo = f2bf(l0) | (f2bf(l1) << 16);
}
__device__ __forceinline__ uint32_t smem_u32(const void* p) {
    uint32_t a;
    asm("{ .reg .u64 t; cvta.to.shared.u64 t, %1; cvt.u32.u64 %0, t; }" : "=r"(a) : "l"(p));
    return a;
}
__device__ __forceinline__ void cp16s(uint32_t saddr, const void* g) {
    asm volatile("cp.async.cg.shared.global [%0], [%1], 16;" :: "r"(saddr), "l"(g));
}
#define LDSM4(r, addr)                                                         \
    asm volatile("ldmatrix.sync.aligned.m8n8.x4.shared.b16 {%0,%1,%2,%3}, [%4];" \
        : "=r"((r)[0]), "=r"((r)[1]), "=r"((r)[2]), "=r"((r)[3]) : "r"(addr))
#define MMA_BF16(c, a, b0, b1)                                                \
    asm volatile(                                                             \
        "mma.sync.aligned.m16n8k16.row.col.f32.bf16.bf16.f32 "                \
        "{%0,%1,%2,%3},{%4,%5,%6,%7},{%8,%9},{%0,%1,%2,%3};"                  \
        : "+f"((c)[0]), "+f"((c)[1]), "+f"((c)[2]), "+f"((c)[3])              \
        : "r"((a)[0]), "r"((a)[1]), "r"((a)[2]), "r"((a)[3]),                 \
          "r"(b0), "r"(b1))

// ---------------- 4-level Haar == 16x16 2D Walsh-Hadamard per tile ----------------
__global__ void haar_kernel(const float* __restrict__ x) {
    int bid  = blockIdx.x;
    int tile = bid % 196;
    int bc   = bid / 196;
    int c    = bc % 3;
    int b    = bc / 3;
    int ti = tile / 14, tj = tile % 14;
    int t  = threadIdx.x;
    int dy = t >> 4, dx = t & 15;

    __shared__ float s[256];
    float v = x[((b * 3 + c) * 224 + ti * 16 + dy) * 224 + tj * 16 + dx];

#pragma unroll
    for (int st = 0; st < 8; ++st) {
        s[t] = v;
        __syncthreads();
        float u = s[t ^ (1 << st)];
        v = (t & (1 << st)) ? (u - v) : (v + u);
        __syncthreads();
    }

    int cm = t & 15, rm = t >> 4;
    int k1 = 2 * ((rm >> 0) & 1) + ((cm >> 0) & 1);
    int k2 = 2 * ((rm >> 1) & 1) + ((cm >> 1) & 1);
    int k3 = 2 * ((rm >> 2) & 1) + ((cm >> 2) & 1);
    int k4 = 2 * ((rm >> 3) & 1) + ((cm >> 3) & 1);
    int k  = ((k1 * 4 + k2) * 4 + k3) * 4 + k4;
    g_wav[((size_t)(b * 196 + tile)) * 768 + (k * 3 + c)] = v * 0.0625f;
}

// ---------------- compose (smem-resident) ----------------
__global__ void __launch_bounds__(256) compose_kernel(const float* __restrict__ w1,
                                                      const float* __restrict__ w2) {
    int o = blockIdx.x / 3, c = blockIdx.x % 3;
    __shared__ float s_w1[192 * 49];
    __shared__ float s_w2[32 * 49];

    for (int i = threadIdx.x; i < 192 * 49; i += 256) {
        int m = i / 49, r = i - m * 49;
        s_w1[i] = w1[m * 147 + c * 49 + r];
    }

    float acc[4] = {0.f, 0.f, 0.f, 0.f};
    bool  uval[4];
    int   oAA2[4], oAA1[4], oAB2[4], oAB1[4], oBA2[4], oBA1[4], oBB2[4], oBB1[4];
    bool  vx[4], vy[4];
#pragma unroll
    for (int u = 0; u < 4; ++u) {
        int idx = threadIdx.x + u * 256;
        uval[u] = (idx < 961);
        int ii = uval[u] ? idx : 0;
        int dy = ii / 31, dx = ii - (ii / 31) * 31;
        int kyA = min(dy >> 2, 6); int ky1A = dy - 4 * kyA;
        vy[u] = (kyA >= 1) && (ky1A + 4 <= 6);
        int kyB = kyA - 1, ky1B = ky1A + 4;
        int kxA = min(dx >> 2, 6); int kx1A = dx - 4 * kxA;
        vx[u] = (kxA >= 1) && (kx1A + 4 <= 6);
        int kxB = kxA - 1, kx1B = kx1A + 4;
        oAA2[u] = kyA * 7 + kxA; oAA1[u] = ky1A * 7 + kx1A;
        oAB2[u] = kyA * 7 + kxB; oAB1[u] = ky1A * 7 + kx1B;
        oBA2[u] = kyB * 7 + kxA; oBA1[u] = ky1B * 7 + kx1A;
        oBB2[u] = kyB * 7 + kxB; oBB1[u] = ky1B * 7 + kx1B;
    }

    for (int mc = 0; mc < 192; mc += 32) {
        __syncthreads();
        for (int i = threadIdx.x; i < 32 * 49; i += 256)
            s_w2[i] = w2[o * 9408 + mc * 49 + i];
        __syncthreads();
#pragma unroll 4
        for (int m = 0; m < 32; ++m) {
            const float* w2m = &s_w2[m * 49];
            const float* w1m = &s_w1[(mc + m) * 49];
#pragma unroll
            for (int u = 0; u < 4; ++u) {
                if (!uval[u]) continue;
                acc[u] += w2m[oAA2[u]] * w1m[oAA1[u]];
                if (vx[u]) acc[u] += w2m[oAB2[u]] * w1m[oAB1[u]];
                if (vy[u]) acc[u] += w2m[oBA2[u]] * w1m[oBA1[u]];
                if (vy[u] && vx[u]) acc[u] += w2m[oBB2[u]] * w1m[oBB1[u]];
            }
        }
    }
#pragma unroll
    for (int u = 0; u < 4; ++u) {
        int idx = threadIdx.x + u * 256;
        if (idx < 961) g_wcomp[o * 2883 + c * 961 + idx] = acc[u];
    }
}

// ---------------- composed bias (4 border cases) ----------------
__global__ void bias_kernel(const float* __restrict__ w2,
                            const float* __restrict__ b1,
                            const float* __restrict__ b2) {
    int o = blockIdx.x;
    int m = threadIdx.x;
    float s00 = 0, s01 = 0, s10 = 0, s11 = 0;
    if (m < 192) {
        float bm = b1[m];
#pragma unroll
        for (int ky2 = 0; ky2 < 7; ++ky2)
#pragma unroll
            for (int kx2 = 0; kx2 < 7; ++kx2) {
                float w = w2[((o * 192 + m) * 7 + ky2) * 7 + kx2] * bm;
                s00 += w;
                if (kx2 >= 3) s01 += w;
                if (ky2 >= 3) s10 += w;
                if (ky2 >= 3 && kx2 >= 3) s11 += w;
            }
    }
    __shared__ float red[4][256];
    red[0][m] = s00; red[1][m] = s01; red[2][m] = s10; red[3][m] = s11;
    __syncthreads();
    for (int s = 128; s > 0; s >>= 1) {
        if (m < s) {
            red[0][m] += red[0][m + s];
            red[1][m] += red[1][m + s];
            red[2][m] += red[2][m + s];
            red[3][m] += red[3][m + s];
        }
        __syncthreads();
    }
    if (m == 0) {
        float bo = b2[o];
        g_bias[o * 4 + 0] = bo + red[0][0];
        g_bias[o * 4 + 1] = bo + red[1][0];
        g_bias[o * 4 + 2] = bo + red[2][0];
        g_bias[o * 4 + 3] = bo + red[3][0];
    }
}

// ---------------- packs (extended-K) ----------------
__global__ void pack_a2() {
    int t = blockIdx.x * 256 + threadIdx.x;      // 192*1472
    int m = t / 1472, j = t - (t / 1472) * 1472;
    int k = 2 * j;
    float v0 = (k     < 2883) ? g_wcomp[m * 2883 + k]     : 0.f;
    float v1 = (k + 1 < 2883) ? g_wcomp[m * 2883 + k + 1] : 0.f;
    unsigned hi, lo;
    split2(v0, v1, hi, lo);
    size_t base = (size_t)m * 4416 + j;
    g_A2e[base] = hi; g_A2e[base + 1472] = lo; g_A2e[base + 2944] = hi;
}
__global__ void pack_a3(const float* __restrict__ wp) {   // k' = r*960 + ch
    int t = blockIdx.x * 256 + threadIdx.x;               // 768*4320
    int m = t / 4320, j = t - (t / 4320) * 4320;
    int kn = 2 * j;
    int r = kn / 960, ch = kn - r * 960;
    float v0 = wp[(size_t)m * 8640 + ch * 9 + r];
    float v1 = wp[(size_t)m * 8640 + (ch + 1) * 9 + r];
    unsigned hi, lo;
    split2(v0, v1, hi, lo);
    size_t base = (size_t)m * 12960 + j;
    g_A3e[base] = hi; g_A3e[base + 4320] = lo; g_A3e[base + 8640] = hi;
}
__global__ void pack_b2(const float* __restrict__ x) {
    int t = blockIdx.x * 256 + threadIdx.x;      // 12544*1472
    int n = t / 1472, j = t - (t / 1472) * 1472;
    int b = n / 196, p = n - (n / 196) * 196;
    int oy = p / 14, ox = p - (p / 14) * 14;
    float v[2];
#pragma unroll
    for (int e = 0; e < 2; ++e) {
        int k = 2 * j + e;
        float vv = 0.f;
        if (k < 2883) {
            int c = k / 961, r = k - c * 961;
            int dy = r / 31, dx = r - (r / 31) * 31;
            int iy = oy * 16 + dy - 15, ix = ox * 16 + dx - 15;
            if ((unsigned)iy < 224u && (unsigned)ix < 224u)
                vv = x[((b * 3 + c) * 224 + iy) * 224 + ix];
        }
        v[e] = vv;
    }
    unsigned hi, lo;
    split2(v[0], v[1], hi, lo);
    size_t base = (size_t)n * 4416 + j;
    g_B2e[base] = hi; g_B2e[base + 1472] = hi; g_B2e[base + 2944] = lo;
}
__global__ void pack_b3() {
    int r = blockIdx.x;          // 0..8
    int n = blockIdx.y;          // 0..3199
    int ky = r / 3, kx = r - ky * 3;
    size_t obase = (size_t)n * 12960 + r * 480;
    if (n >= 3136) {
        for (int cp = threadIdx.x; cp < 480; cp += 128) {
            g_B3e[obase + cp] = 0; g_B3e[obase + 4320 + cp] = 0; g_B3e[obase + 8640 + cp] = 0;
        }
        return;
    }
    int b = n / 49, p = n - b * 49;
    int oy = p / 7, ox = p - oy * 7;
    int iy = oy * 2 + ky - 1, ix = ox * 2 + kx - 1;
    bool inb = ((unsigned)iy < 14u) && ((unsigned)ix < 14u);
    const float* wavp = &g_wav[((size_t)(b * 196 + (inb ? iy * 14 + ix : 0))) * 768];
    const float* sp2p = &g_sp2[((size_t)(b * 196 + (inb ? iy * 14 + ix : 0))) * 192];
    for (int cp = threadIdx.x; cp < 480; cp += 128) {
        int ch = 2 * cp;
        float v0 = 0.f, v1 = 0.f;
        if (inb) {
            v0 = (ch < 768) ? wavp[ch] : sp2p[ch - 768];
            v1 = (ch + 1 < 768) ? wavp[ch + 1] : sp2p[ch + 1 - 768];
        }
        unsigned hi, lo;
        split2(v0, v1, hi, lo);
        g_B3e[obase + cp] = hi; g_B3e[obase + 4320 + cp] = hi; g_B3e[obase + 8640 + cp] = lo;
    }
}

// ---------------- HMMA GEMM: warp tile 64x64, BK=32, 3-stage cp.async ------------
template <int MODE>
__global__ void __launch_bounds__((MODE == 2) ? 192 : 128)
gemm_mma(const float* __restrict__ bias,
         const float* __restrict__ positions,
         float* __restrict__ Cout)
{
    constexpr int BN   = (MODE == 2) ? 192 : 128;
    constexpr int THR  = (MODE == 2) ? 192 : 128;
    constexpr int NWN  = BN / 64;
    constexpr int KU   = (MODE == 2) ? 4416 : 12960;
    constexpr int NIT  = (MODE == 2) ? 276  : 810;
    constexpr int ROWS = 128 + BN;
    constexpr int PB   = 80;

    extern __shared__ __align__(16) char smem[];
    const uint32_t sb = smem_u32(smem);

    const unsigned* Ae = (MODE == 2) ? g_B2e : g_B3e;   // patches
    const unsigned* Be = (MODE == 2) ? g_A2e : g_A3e;   // weights

    const int tid = threadIdx.x, wid = tid >> 5, lane = tid & 31;
    const int grp = lane >> 2, tig = lane & 3;
    const int m0  = blockIdx.x * 128;
    const int oc0 = (MODE == 2) ? 0 : blockIdx.y * 128;
    const int wm  = (wid / NWN) * 64;
    const int wn  = (wid % NWN) * 64;

    float acc[4][8][4] = {};

    auto stage = [&](int buf, int it) {
        uint32_t base = sb + buf * (ROWS * PB);
        const int ko = it * 16;
        for (int idx = tid; idx < ROWS * 4; idx += THR) {
            int row = idx >> 2, c = idx & 3;
            uint32_t sa = base + row * PB + c * 16;
            const unsigned* g = (row < 128)
                ? Ae + (size_t)(m0 + row) * KU + ko + c * 4
                : Be + (size_t)(oc0 + row - 128) * KU + ko + c * 4;
            cp16s(sa, g);
        }
        asm volatile("cp.async.commit_group;");
    };

    stage(0, 0);
    stage(1, 1);

    for (int it = 0; it < NIT; ++it) {
        const int buf = it % 3;
        asm volatile("cp.async.wait_group 1;");
        __syncthreads();

        const uint32_t aw = sb + buf * (ROWS * PB);
        const uint32_t bw = aw + 128 * PB;
#pragma unroll
        for (int s = 0; s < 2; ++s) {
            unsigned a[4][4], bf[4][4];
#pragma unroll
            for (int mf = 0; mf < 4; ++mf) {
                uint32_t addr = aw +
                    (wm + mf * 16 + (lane & 7) + ((lane >> 3) & 1) * 8) * PB +
                    (2 * s + (lane >> 4)) * 16;
                LDSM4(a[mf], addr);
            }
#pragma unroll
            for (int np = 0; np < 4; ++np) {
                uint32_t addr = bw +
                    (wn + np * 16 + (lane & 7) + ((lane >> 4) & 1) * 8) * PB +
                    (2 * s + ((lane >> 3) & 1)) * 16;
                LDSM4(bf[np], addr);
            }
#pragma unroll
            for (int mf = 0; mf < 4; ++mf)
#pragma unroll
                for (int np = 0; np < 4; ++np) {
                    MMA_BF16(acc[mf][2 * np],     a[mf], bf[np][0], bf[np][1]);
                    MMA_BF16(acc[mf][2 * np + 1], a[mf], bf[np][2], bf[np][3]);
                }
        }
        if (it + 2 < NIT) stage((it + 2) % 3, it + 2);
        else              asm volatile("cp.async.commit_group;");
    }

    // ---- epilogue ----
#pragma unroll
    for (int mf = 0; mf < 4; ++mf) {
#pragma unroll
        for (int h = 0; h < 2; ++h) {
            int row = m0 + wm + mf * 16 + grp + h * 8;   // patch index
            if (MODE == 2) {
                int b = row / 196, p = row - (row / 196) * 196;
                int oy = p / 14, ox = p - (p / 14) * 14;
                int bc = (oy == 0 ? 2 : 0) + (ox == 0 ? 1 : 0);
                float* dst = &g_sp2[((size_t)(b * 196 + p)) * 192];
#pragma unroll
                for (int nf = 0; nf < 8; ++nf) {
                    int col = wn + nf * 8 + 2 * tig;
                    float2 v;
                    v.x = acc[mf][nf][2 * h]     + g_bias[col * 4 + bc];
                    v.y = acc[mf][nf][2 * h + 1] + g_bias[(col + 1) * 4 + bc];
                    *(float2*)(dst + col) = v;
                }
            } else {
                if (row < 3136) {
                    int b = row / 49, p = row - (row / 49) * 49;
                    float* dst = Cout + ((size_t)(b * 50 + 1 + p)) * 768 + oc0;
                    const float* pp = positions + (size_t)(1 + p) * 768 + oc0;
#pragma unroll
                    for (int nf = 0; nf < 8; ++nf) {
                        int col = wn + nf * 8 + 2 * tig;
                        float2 v;
                        v.x = acc[mf][nf][2 * h]     + bias[oc0 + col]     + pp[col];
                        v.y = acc[mf][nf][2 * h + 1] + bias[oc0 + col + 1] + pp[col + 1];
                        *(float2*)(dst + col) = v;
                    }
                }
            }
        }
    }
}

// ---------------- cls row ----------------
__global__ void cls_kernel(const float* __restrict__ cls,
                           const float* __restrict__ pos,
                           float* __restrict__ out) {
    int i = blockIdx.x * 256 + threadIdx.x;
    if (i < 64 * 768) {
        int b = i / 768, oc = i % 768;
        out[(b * 50) * 768 + oc] = cls[oc] + pos[oc];
    }
}

extern "C" void kernel_launch(void* const* d_in, const int* in_sizes, int n_in,
                              void* d_out, int out_size) {
    const float* x   = (const float*)d_in[0];
    const float* w1  = (const float*)d_in[1];
    const float* b1  = (const float*)d_in[2];
    const float* w2  = (const float*)d_in[3];
    const float* b2  = (const float*)d_in[4];
    const float* wp  = (const float*)d_in[5];
    const float* bp  = (const float*)d_in[6];
    const float* cls = (const float*)d_in[7];
    const float* pos = (const float*)d_in[8];
    float* out = (float*)d_out;

    const int SM2 = 3 * (128 + 192) * 80;   // 76800 B
    const int SM3 = 3 * (128 + 128) * 80;   // 61440 B
    cudaFuncSetAttribute(gemm_mma<2>, cudaFuncAttributeMaxDynamicSharedMemorySize, SM2);
    cudaFuncSetAttribute(gemm_mma<3>, cudaFuncAttributeMaxDynamicSharedMemorySize, SM3);

    haar_kernel<<<64 * 3 * 196, 256>>>(x);
    compose_kernel<<<576, 256>>>(w1, w2);
    bias_kernel<<<192, 256>>>(w2, b1, b2);

    pack_a2<<<192 * 1472 / 256, 256>>>();
    pack_a3<<<768 * 4320 / 256, 256>>>(wp);
    pack_b2<<<12544 * 1472 / 256, 256>>>(x);

    gemm_mma<2><<<dim3(98, 1), 192, SM2>>>(nullptr, nullptr, nullptr);

    pack_b3<<<dim3(9, 3200), 128>>>();

    gemm_mma<3><<<dim3(25, 6), 128, SM3>>>(bp, pos, out);

    cls_kernel<<<192, 256>>>(cls, pos, out);
}

// round 13
// speedup vs baseline: 1.7124x; 1.7124x over previous
#include <cuda_runtime.h>
#include <cstdint>

// ---------------- scratch (static device globals; no allocation) ----------------
__device__ __align__(16) float g_wav[64 * 196 * 768];   // channel-last [b][p][768]
__device__ __align__(16) float g_sp2[64 * 196 * 192];   // channel-last [b][p][192]
__device__ __align__(16) float g_wcomp[192 * 3 * 31 * 31];
__device__ __align__(16) float g_bias[192 * 4];

// bf16 hi/lo planes (u32 = 2 bf16), K-major rows
// gemm2: K=2883 pad 2944 -> KU2=1472 u32/row
// gemm3: K=8640 tap-major (k' = r*960 + ch) -> KU3=4320 u32/row
__device__ __align__(16) unsigned g_A2h[192 * 1472],   g_A2l[192 * 1472];
__device__ __align__(16) unsigned g_A3h[768 * 4320],   g_A3l[768 * 4320];
__device__ __align__(16) unsigned g_B2h[12544u * 1472], g_B2l[12544u * 1472];
__device__ __align__(16) unsigned g_B3h[3200 * 4320],   g_B3l[3200 * 4320];

// ---------------- helpers ----------------
__device__ __forceinline__ unsigned f2bf(float f) {
    unsigned u = __float_as_uint(f);
    return (u + 0x7fffu + ((u >> 16) & 1u)) >> 16;
}
__device__ __forceinline__ void split2(float v0, float v1, unsigned& hi, unsigned& lo) {
    unsigned h0 = f2bf(v0), h1 = f2bf(v1);
    float l0 = v0 - __uint_as_float(h0 << 16);
    float l1 = v1 - __uint_as_float(h1 << 16);
    hi = h0 | (h1 << 16);
    lo = f2bf(l0) | (f2bf(l1) << 16);
}
__device__ __forceinline__ uint32_t smem_u32(const void* p) {
    uint32_t a;
    asm("{ .reg .u64 t; cvta.to.shared.u64 t, %1; cvt.u32.u64 %0, t; }" : "=r"(a) : "l"(p));
    return a;
}
__device__ __forceinline__ void cp16s(uint32_t saddr, const void* g) {
    asm volatile("cp.async.cg.shared.global [%0], [%1], 16;" :: "r"(saddr), "l"(g));
}
#define LDSM4(r, addr)                                                         \
    asm volatile("ldmatrix.sync.aligned.m8n8.x4.shared.b16 {%0,%1,%2,%3}, [%4];" \
        : "=r"((r)[0]), "=r"((r)[1]), "=r"((r)[2]), "=r"((r)[3]) : "r"(addr))
#define MMA_BF16(c, a, b0, b1)                                                \
    asm volatile(                                                             \
        "mma.sync.aligned.m16n8k16.row.col.f32.bf16.bf16.f32 "                \
        "{%0,%1,%2,%3},{%4,%5,%6,%7},{%8,%9},{%0,%1,%2,%3};"                  \
        : "+f"((c)[0]), "+f"((c)[1]), "+f"((c)[2]), "+f"((c)[3])              \
        : "r"((a)[0]), "r"((a)[1]), "r"((a)[2]), "r"((a)[3]),                 \
          "r"(b0), "r"(b1))

// ---------------- 4-level Haar == 16x16 2D Walsh-Hadamard per tile ----------------
__global__ void haar_kernel(const float* __restrict__ x) {
    int bid  = blockIdx.x;
    int tile = bid % 196;
    int bc   = bid / 196;
    int c    = bc % 3;
    int b    = bc / 3;
    int ti = tile / 14, tj = tile % 14;
    int t  = threadIdx.x;
    int dy = t >> 4, dx = t & 15;

    __shared__ float s[256];
    float v = x[((b * 3 + c) * 224 + ti * 16 + dy) * 224 + tj * 16 + dx];

#pragma unroll
    for (int st = 0; st < 8; ++st) {
        s[t] = v;
        __syncthreads();
        float u = s[t ^ (1 << st)];
        v = (t & (1 << st)) ? (u - v) : (v + u);
        __syncthreads();
    }

    int cm = t & 15, rm = t >> 4;
    int k1 = 2 * ((rm >> 0) & 1) + ((cm >> 0) & 1);
    int k2 = 2 * ((rm >> 1) & 1) + ((cm >> 1) & 1);
    int k3 = 2 * ((rm >> 2) & 1) + ((cm >> 2) & 1);
    int k4 = 2 * ((rm >> 3) & 1) + ((cm >> 3) & 1);
    int k  = ((k1 * 4 + k2) * 4 + k3) * 4 + k4;
    g_wav[((size_t)(b * 196 + tile)) * 768 + (k * 3 + c)] = v * 0.0625f;
}

// ---------------- compose (smem-resident) ----------------
__global__ void __launch_bounds__(256) compose_kernel(const float* __restrict__ w1,
                                                      const float* __restrict__ w2) {
    int o = blockIdx.x / 3, c = blockIdx.x % 3;
    __shared__ float s_w1[192 * 49];
    __shared__ float s_w2[32 * 49];

    for (int i = threadIdx.x; i < 192 * 49; i += 256) {
        int m = i / 49, r = i - m * 49;
        s_w1[i] = w1[m * 147 + c * 49 + r];
    }

    float acc[4] = {0.f, 0.f, 0.f, 0.f};
    bool  uval[4];
    int   oAA2[4], oAA1[4], oAB2[4], oAB1[4], oBA2[4], oBA1[4], oBB2[4], oBB1[4];
    bool  vx[4], vy[4];
#pragma unroll
    for (int u = 0; u < 4; ++u) {
        int idx = threadIdx.x + u * 256;
        uval[u] = (idx < 961);
        int ii = uval[u] ? idx : 0;
        int dy = ii / 31, dx = ii - (ii / 31) * 31;
        int kyA = min(dy >> 2, 6); int ky1A = dy - 4 * kyA;
        vy[u] = (kyA >= 1) && (ky1A + 4 <= 6);
        int kyB = kyA - 1, ky1B = ky1A + 4;
        int kxA = min(dx >> 2, 6); int kx1A = dx - 4 * kxA;
        vx[u] = (kxA >= 1) && (kx1A + 4 <= 6);
        int kxB = kxA - 1, kx1B = kx1A + 4;
        oAA2[u] = kyA * 7 + kxA; oAA1[u] = ky1A * 7 + kx1A;
        oAB2[u] = kyA * 7 + kxB; oAB1[u] = ky1A * 7 + kx1B;
        oBA2[u] = kyB * 7 + kxA; oBA1[u] = ky1B * 7 + kx1A;
        oBB2[u] = kyB * 7 + kxB; oBB1[u] = ky1B * 7 + kx1B;
    }

    for (int mc = 0; mc < 192; mc += 32) {
        __syncthreads();
        for (int i = threadIdx.x; i < 32 * 49; i += 256)
            s_w2[i] = w2[o * 9408 + mc * 49 + i];
        __syncthreads();
#pragma unroll 4
        for (int m = 0; m < 32; ++m) {
            const float* w2m = &s_w2[m * 49];
            const float* w1m = &s_w1[(mc + m) * 49];
#pragma unroll
            for (int u = 0; u < 4; ++u) {
                if (!uval[u]) continue;
                acc[u] += w2m[oAA2[u]] * w1m[oAA1[u]];
                if (vx[u]) acc[u] += w2m[oAB2[u]] * w1m[oAB1[u]];
                if (vy[u]) acc[u] += w2m[oBA2[u]] * w1m[oBA1[u]];
                if (vy[u] && vx[u]) acc[u] += w2m[oBB2[u]] * w1m[oBB1[u]];
            }
        }
    }
#pragma unroll
    for (int u = 0; u < 4; ++u) {
        int idx = threadIdx.x + u * 256;
        if (idx < 961) g_wcomp[o * 2883 + c * 961 + idx] = acc[u];
    }
}

// ---------------- composed bias (4 border cases) ----------------
__global__ void bias_kernel(const float* __restrict__ w2,
                            const float* __restrict__ b1,
                            const float* __restrict__ b2) {
    int o = blockIdx.x;
    int m = threadIdx.x;
    float s00 = 0, s01 = 0, s10 = 0, s11 = 0;
    if (m < 192) {
        float bm = b1[m];
#pragma unroll
        for (int ky2 = 0; ky2 < 7; ++ky2)
#pragma unroll
            for (int kx2 = 0; kx2 < 7; ++kx2) {
                float w = w2[((o * 192 + m) * 7 + ky2) * 7 + kx2] * bm;
                s00 += w;
                if (kx2 >= 3) s01 += w;
                if (ky2 >= 3) s10 += w;
                if (ky2 >= 3 && kx2 >= 3) s11 += w;
            }
    }
    __shared__ float red[4][256];
    red[0][m] = s00; red[1][m] = s01; red[2][m] = s10; red[3][m] = s11;
    __syncthreads();
    for (int s = 128; s > 0; s >>= 1) {
        if (m < s) {
            red[0][m] += red[0][m + s];
            red[1][m] += red[1][m + s];
            red[2][m] += red[2][m + s];
            red[3][m] += red[3][m + s];
        }
        __syncthreads();
    }
    if (m == 0) {
        float bo = b2[o];
        g_bias[o * 4 + 0] = bo + red[0][0];
        g_bias[o * 4 + 1] = bo + red[1][0];
        g_bias[o * 4 + 2] = bo + red[2][0];
        g_bias[o * 4 + 3] = bo + red[3][0];
    }
}

// ---------------- packs (hi/lo planes) ----------------
__global__ void pack_a2() {
    int t = blockIdx.x * 256 + threadIdx.x;      // 192*1472
    int m = t / 1472, j = t - (t / 1472) * 1472;
    int k = 2 * j;
    float v0 = (k     < 2883) ? g_wcomp[m * 2883 + k]     : 0.f;
    float v1 = (k + 1 < 2883) ? g_wcomp[m * 2883 + k + 1] : 0.f;
    split2(v0, v1, g_A2h[t], g_A2l[t]);
}
__global__ void pack_a3(const float* __restrict__ wp) {   // k' = r*960 + ch
    int t = blockIdx.x * 256 + threadIdx.x;               // 768*4320
    int m = t / 4320, j = t - (t / 4320) * 4320;
    int kn = 2 * j;
    int r = kn / 960, ch = kn - r * 960;
    float v0 = wp[(size_t)m * 8640 + ch * 9 + r];
    float v1 = wp[(size_t)m * 8640 + (ch + 1) * 9 + r];
    split2(v0, v1, g_A3h[t], g_A3l[t]);
}
__global__ void pack_b2(const float* __restrict__ x) {
    int t = blockIdx.x * 256 + threadIdx.x;      // 12544*1472
    int n = t / 1472, j = t - (t / 1472) * 1472;
    int b = n / 196, p = n - (n / 196) * 196;
    int oy = p / 14, ox = p - (p / 14) * 14;
    float v[2];
#pragma unroll
    for (int e = 0; e < 2; ++e) {
        int k = 2 * j + e;
        float vv = 0.f;
        if (k < 2883) {
            int c = k / 961, r = k - c * 961;
            int dy = r / 31, dx = r - (r / 31) * 31;
            int iy = oy * 16 + dy - 15, ix = ox * 16 + dx - 15;
            if ((unsigned)iy < 224u && (unsigned)ix < 224u)
                vv = x[((b * 3 + c) * 224 + iy) * 224 + ix];
        }
        v[e] = vv;
    }
    split2(v[0], v[1], g_B2h[t], g_B2l[t]);
}
__global__ void pack_b3() {
    int r = blockIdx.x;          // 0..8 (tap)
    int n = blockIdx.y;          // 0..3199
    int ky = r / 3, kx = r - ky * 3;
    size_t obase = (size_t)n * 4320 + r * 480;
    if (n >= 3136) {
        for (int cp = threadIdx.x; cp < 480; cp += 128) {
            g_B3h[obase + cp] = 0; g_B3l[obase + cp] = 0;
        }
        return;
    }
    int b = n / 49, p = n - b * 49;
    int oy = p / 7, ox = p - oy * 7;
    int iy = oy * 2 + ky - 1, ix = ox * 2 + kx - 1;
    bool inb = ((unsigned)iy < 14u) && ((unsigned)ix < 14u);
    const float* wavp = &g_wav[((size_t)(b * 196 + (inb ? iy * 14 + ix : 0))) * 768];
    const float* sp2p = &g_sp2[((size_t)(b * 196 + (inb ? iy * 14 + ix : 0))) * 192];
    for (int cp = threadIdx.x; cp < 480; cp += 128) {
        int ch = 2 * cp;
        float v0 = 0.f, v1 = 0.f;
        if (inb) {
            v0 = (ch < 768) ? wavp[ch] : sp2p[ch - 768];
            v1 = (ch + 1 < 768) ? wavp[ch + 1] : sp2p[ch + 1 - 768];
        }
        unsigned hi, lo;
        split2(v0, v1, hi, lo);
        g_B3h[obase + cp] = hi;
        g_B3l[obase + cp] = lo;
    }
}

// ---------------- HMMA GEMM: hi/lo planes, 3-pass in-register, BK=32, 3-stage ----
// MODE 2: block 128patch x 64oc, warp 64x16, grid (98, 3)
// MODE 3: block 128patch x 128oc, warp 64x32, grid (25, 6)
template <int MODE>
__global__ void __launch_bounds__(256, 1)
gemm_mma(const float* __restrict__ bias,
         const float* __restrict__ positions,
         float* __restrict__ Cout)
{
    constexpr int BNR  = (MODE == 2) ? 64 : 128;     // oc rows per block
    constexpr int NP   = (MODE == 2) ? 1 : 2;        // 16-col groups per warp
    constexpr int KU   = (MODE == 2) ? 1472 : 4320;  // u32 per row per plane
    constexpr int NIT  = (MODE == 2) ? 92 : 270;     // K/32
    constexpr int ROWS = 128 + BNR;                  // rows per plane
    constexpr int PB   = 80;                         // pitch bytes (64 data + 16 pad)
    constexpr int STAGE = 2 * ROWS * PB;             // hi plane + lo plane

    extern __shared__ __align__(16) char smem[];
    const uint32_t sb = smem_u32(smem);

    const unsigned* Ah = (MODE == 2) ? g_B2h : g_B3h;   // patches
    const unsigned* Al = (MODE == 2) ? g_B2l : g_B3l;
    const unsigned* Bh = (MODE == 2) ? g_A2h : g_A3h;   // weights
    const unsigned* Bl = (MODE == 2) ? g_A2l : g_A3l;

    const int tid = threadIdx.x, wid = tid >> 5, lane = tid & 31;
    const int grp = lane >> 2, tig = lane & 3;
    const int m0  = blockIdx.x * 128;
    const int oc0 = blockIdx.y * BNR;
    const int wm  = (wid >> 2) * 64;
    const int wn  = (wid & 3) * (16 * NP);

    float acc[4][2 * NP][4] = {};

    auto stage = [&](int buf, int it) {
        const uint32_t base = sb + buf * STAGE;
        const int ko = it * 16;
#pragma unroll
        for (int idx = tid; idx < 2 * ROWS * 4; idx += 256) {
            int c  = idx & 3;
            int rr = idx >> 2;
            int r2 = (rr >= ROWS) ? rr - ROWS : rr;
            const unsigned* src;
            if (rr < ROWS)
                src = (r2 < 128) ? Ah + (size_t)(m0 + r2) * KU
                                 : Bh + (size_t)(oc0 + r2 - 128) * KU;
            else
                src = (r2 < 128) ? Al + (size_t)(m0 + r2) * KU
                                 : Bl + (size_t)(oc0 + r2 - 128) * KU;
            cp16s(base + rr * PB + c * 16, src + ko + c * 4);
        }
        asm volatile("cp.async.commit_group;");
    };

    stage(0, 0);
    stage(1, 1);

    for (int it = 0; it < NIT; ++it) {
        const int buf = it % 3;
        asm volatile("cp.async.wait_group 1;");
        __syncthreads();

        const uint32_t awh = sb + buf * STAGE;
        const uint32_t bwh = awh + 128 * PB;
        const uint32_t awl = awh + ROWS * PB;
        const uint32_t bwl = awl + 128 * PB;

#pragma unroll
        for (int s = 0; s < 2; ++s) {
            unsigned ah[4][4], al[4][4], bh[NP][4], bl[NP][4];
#pragma unroll
            for (int mf = 0; mf < 4; ++mf) {
                uint32_t off = (wm + mf * 16 + (lane & 15)) * PB + (lane >> 4) * 16 + s * 32;
                LDSM4(ah[mf], awh + off);
                LDSM4(al[mf], awl + off);
            }
#pragma unroll
            for (int np = 0; np < NP; ++np) {
                uint32_t off = (wn + np * 16 + (lane & 7) + ((lane >> 4) & 1) * 8) * PB +
                               ((lane >> 3) & 1) * 16 + s * 32;
                LDSM4(bh[np], bwh + off);
                LDSM4(bl[np], bwl + off);
            }
#pragma unroll
            for (int mf = 0; mf < 4; ++mf)
#pragma unroll
                for (int np = 0; np < NP; ++np) {
                    MMA_BF16(acc[mf][2 * np],     ah[mf], bh[np][0], bh[np][1]);
                    MMA_BF16(acc[mf][2 * np + 1], ah[mf], bh[np][2], bh[np][3]);
                    MMA_BF16(acc[mf][2 * np],     ah[mf], bl[np][0], bl[np][1]);
                    MMA_BF16(acc[mf][2 * np + 1], ah[mf], bl[np][2], bl[np][3]);
                    MMA_BF16(acc[mf][2 * np],     al[mf], bh[np][0], bh[np][1]);
                    MMA_BF16(acc[mf][2 * np + 1], al[mf], bh[np][2], bh[np][3]);
                }
        }
        if (it + 2 < NIT) stage((it + 2) % 3, it + 2);
        else              asm volatile("cp.async.commit_group;");
    }

    // ---- epilogue ----
#pragma unroll
    for (int mf = 0; mf < 4; ++mf) {
#pragma unroll
        for (int h = 0; h < 2; ++h) {
            int row = m0 + wm + mf * 16 + grp + h * 8;   // patch index
            if (MODE == 2) {
                int b = row / 196, p = row - (row / 196) * 196;
                int oy = p / 14, ox = p - (p / 14) * 14;
                int bc = (oy == 0 ? 2 : 0) + (ox == 0 ? 1 : 0);
                float* dst = &g_sp2[((size_t)(b * 196 + p)) * 192] + oc0;
#pragma unroll
                for (int nf = 0; nf < 2 * NP; ++nf) {
                    int col = wn + nf * 8 + 2 * tig;
                    float2 v;
                    v.x = acc[mf][nf][2 * h]     + g_bias[(oc0 + col) * 4 + bc];
                    v.y = acc[mf][nf][2 * h + 1] + g_bias[(oc0 + col + 1) * 4 + bc];
                    *(float2*)(dst + col) = v;
                }
            } else {
                if (row < 3136) {
                    int b = row / 49, p = row - (row / 49) * 49;
                    float* dst = Cout + ((size_t)(b * 50 + 1 + p)) * 768 + oc0;
                    const float* pp = positions + (size_t)(1 + p) * 768 + oc0;
#pragma unroll
                    for (int nf = 0; nf < 2 * NP; ++nf) {
                        int col = wn + nf * 8 + 2 * tig;
                        float2 v;
                        v.x = acc[mf][nf][2 * h]     + bias[oc0 + col]     + pp[col];
                        v.y = acc[mf][nf][2 * h + 1] + bias[oc0 + col + 1] + pp[col + 1];
                        *(float2*)(dst + col) = v;
                    }
                }
            }
        }
    }
}

// ---------------- cls row ----------------
__global__ void cls_kernel(const float* __restrict__ cls,
                           const float* __restrict__ pos,
                           float* __restrict__ out) {
    int i = blockIdx.x * 256 + threadIdx.x;
    if (i < 64 * 768) {
        int b = i / 768, oc = i % 768;
        out[(b * 50) * 768 + oc] = cls[oc] + pos[oc];
    }
}

extern "C" void kernel_launch(void* const* d_in, const int* in_sizes, int n_in,
                              void* d_out, int out_size) {
    const float* x   = (const float*)d_in[0];
    const float* w1  = (const float*)d_in[1];
    const float* b1  = (const float*)d_in[2];
    const float* w2  = (const float*)d_in[3];
    const float* b2  = (const float*)d_in[4];
    const float* wp  = (const float*)d_in[5];
    const float* bp  = (const float*)d_in[6];
    const float* cls = (const float*)d_in[7];
    const float* pos = (const float*)d_in[8];
    float* out = (float*)d_out;

    const int SM2 = 3 * 2 * (128 + 64) * 80;    // 92160 B
    const int SM3 = 3 * 2 * (128 + 128) * 80;   // 122880 B
    cudaFuncSetAttribute(gemm_mma<2>, cudaFuncAttributeMaxDynamicSharedMemorySize, SM2);
    cudaFuncSetAttribute(gemm_mma<3>, cudaFuncAttributeMaxDynamicSharedMemorySize, SM3);

    haar_kernel<<<64 * 3 * 196, 256>>>(x);
    compose_kernel<<<576, 256>>>(w1, w2);
    bias_kernel<<<192, 256>>>(w2, b1, b2);

    pack_a2<<<192 * 1472 / 256, 256>>>();
    pack_a3<<<768 * 4320 / 256, 256>>>(wp);
    pack_b2<<<12544 * 1472 / 256, 256>>>(x);

    gemm_mma<2><<<dim3(98, 3), 256, SM2>>>(nullptr, nullptr, nullptr);

    pack_b3<<<dim3(9, 3200), 128>>>();

    gemm_mma<3><<<dim3(25, 6), 256, SM3>>>(bp, pos, out);

    cls_kernel<<<192, 256>>>(cls, pos, out);
}